// round 4
// baseline (speedup 1.0000x reference)
#include <cuda_runtime.h>
#include <math.h>

#define NB    128
#define NTH   256
#define BB    64
#define TT    512
#define IND   512
#define XD    1024
#define OUTD  256

// ------------------------- device scratch (no allocs allowed) -------------
__device__ float g_actin[(size_t)BB * TT * XD];   // [t*64+b][XD], 128 MB
__device__ float g_P[(size_t)BB * TT * XD];       // [t*64+b][XD], 128 MB
__device__ float g_h1[BB * XD];
__device__ float g_h2[BB * XD];
__device__ float g_h3[BB * XD];
__device__ float g_rs[2][BB * XD];
__device__ float g_normpart[16][BB];              // per-tile partial sumsq of rs rows
__device__ float g_part[20 * 8 * 64 * 64];        // k-split partial slabs
__device__ unsigned g_tilecnt[20];
__device__ unsigned g_barcnt;
__device__ unsigned g_bargen;

// ------------------------- activation (matches reference) -----------------
__device__ __forceinline__ float rand_act(float v, int idx, float mx) {
    float r;
    switch (idx) {
    case 0:  r = fmaxf(v, 0.0f); break;                       // ReLU
    case 1:  r = 1.0f / (1.0f + expf(-v)); break;             // Sigmoid
    case 2:  r = tanhf(v); break;                             // Tanh
    case 3:  r = (v >= 0.0f) ? v : 0.1f * v; break;           // LeakyReLU(0.1)
    default: {                                                // SELU
        const float a = 1.6732632423543772f, s = 1.0507009873554805f;
        r = (v > 0.0f) ? s * v : s * a * expm1f(v);
    } break;
    }
    return fminf(r, mx);
}

__device__ __forceinline__ float4 act4(float4 v, int4 id, float4 mx) {
    return make_float4(rand_act(v.x, id.x, mx.x), rand_act(v.y, id.y, mx.y),
                       rand_act(v.z, id.z, mx.z), rand_act(v.w, id.w, mx.w));
}

// ------------------------- grid-wide barrier -------------------------------
__device__ __forceinline__ void gsync(unsigned& mygen) {
    __threadfence();
    __syncthreads();
    if (threadIdx.x == 0) {
        unsigned old = atomicAdd(&g_barcnt, 1u);
        if (old == NB - 1u) {
            g_barcnt = 0u;
            __threadfence();
            atomicAdd(&g_bargen, 1u);
        } else {
            while (((volatile unsigned*)&g_bargen)[0] == mygen) { __nanosleep(64); }
        }
    }
    __syncthreads();
    mygen += 1u;
}

// ------------------------- 64x64 tile GEMM, C = A(64,K) * B(64,K)^T --------
// A loaded with __ldcg (mutable inter-block data), B with __ldg (constants).
// Double-buffered shared, one __syncthreads per 16-k chunk.
__device__ __forceinline__ void gemm_tile(const float* __restrict__ Ap, int lda,
                                          const float* __restrict__ Bp, int ldb,
                                          int K, float acc[4][4],
                                          float (&As)[2][16][68],
                                          float (&Bs)[2][16][68]) {
    const int tid  = threadIdx.x;
    const int tx   = tid & 15;
    const int ty   = tid >> 4;
    const int lrow = tid >> 2;
    const int lk   = (tid & 3) << 2;
    const float* aptr = Ap + (size_t)lrow * lda + lk;
    const float* bptr = Bp + (size_t)lrow * ldb + lk;

    float4 av = __ldcg((const float4*)aptr);
    float4 bv = __ldg((const float4*)bptr);
    int p = 0;
    for (int kc = 0; kc < K; kc += 16) {
        As[p][lk + 0][lrow] = av.x; As[p][lk + 1][lrow] = av.y;
        As[p][lk + 2][lrow] = av.z; As[p][lk + 3][lrow] = av.w;
        Bs[p][lk + 0][lrow] = bv.x; Bs[p][lk + 1][lrow] = bv.y;
        Bs[p][lk + 2][lrow] = bv.z; Bs[p][lk + 3][lrow] = bv.w;
        __syncthreads();
        if (kc + 16 < K) {
            av = __ldcg((const float4*)(aptr + kc + 16));
            bv = __ldg((const float4*)(bptr + kc + 16));
        }
#pragma unroll
        for (int kk = 0; kk < 16; kk++) {
            float4 a = *(const float4*)&As[p][kk][ty << 2];
            float4 b = *(const float4*)&Bs[p][kk][tx << 2];
            acc[0][0] += a.x * b.x; acc[0][1] += a.x * b.y; acc[0][2] += a.x * b.z; acc[0][3] += a.x * b.w;
            acc[1][0] += a.y * b.x; acc[1][1] += a.y * b.y; acc[1][2] += a.y * b.z; acc[1][3] += a.y * b.w;
            acc[2][0] += a.z * b.x; acc[2][1] += a.z * b.y; acc[2][2] += a.z * b.z; acc[2][3] += a.z * b.w;
            acc[3][0] += a.w * b.x; acc[3][1] += a.w * b.y; acc[3][2] += a.w * b.z; acc[3][3] += a.w * b.w;
        }
        p ^= 1;
    }
    __syncthreads();
}

// ------------------------- k-split finish ----------------------------------
// Writes this block's partial slab; last-arriving block (per tile counter)
// sums the 7 peer slabs into acc and returns true (it runs the epilogue).
__device__ __forceinline__ bool ksplit_reduce(int tileIdx, int sp, float acc[4][4]) {
    const int tid = threadIdx.x;
    const int tx  = tid & 15;
    const int ty  = tid >> 4;
    float* slab = &g_part[((size_t)tileIdx * 8 + sp) * 4096];
#pragma unroll
    for (int i = 0; i < 4; i++) {
        float4 v = make_float4(acc[i][0], acc[i][1], acc[i][2], acc[i][3]);
        __stcg((float4*)&slab[((ty << 2) + i) * 64 + (tx << 2)], v);
    }
    __threadfence();
    __syncthreads();
    __shared__ int s_last;
    if (tid == 0) {
        unsigned old = atomicAdd(&g_tilecnt[tileIdx], 1u);
        s_last = (old == 7u);
        if (old == 7u) g_tilecnt[tileIdx] = 0u;   // reset for next step (safe: no touchers until after next gsync)
    }
    __syncthreads();
    if (!s_last) return false;
    __threadfence();
#pragma unroll
    for (int s = 0; s < 8; s++) {
        if (s == sp) continue;
        const float* os = &g_part[((size_t)tileIdx * 8 + s) * 4096];
#pragma unroll
        for (int i = 0; i < 4; i++) {
            float4 pv = __ldcg((const float4*)&os[((ty << 2) + i) * 64 + (tx << 2)]);
            acc[i][0] += pv.x; acc[i][1] += pv.y; acc[i][2] += pv.z; acc[i][3] += pv.w;
        }
    }
    return true;
}

// ------------------------- main persistent kernel --------------------------
__global__ void __launch_bounds__(NTH, 1)
bnn_kernel(const float* __restrict__ x,
           const float* __restrict__ Wi,  const float* __restrict__ bi,
           const float* __restrict__ Wh1, const float* __restrict__ bh1,
           const float* __restrict__ Wh2, const float* __restrict__ bh2,
           const float* __restrict__ Wh3, const float* __restrict__ bh3,
           const float* __restrict__ Wo,  const float* __restrict__ bo,
           const float* __restrict__ Wr,  const float* __restrict__ br,
           const float* __restrict__ max_in,  const float* __restrict__ max_h1,
           const float* __restrict__ max_h2,  const float* __restrict__ max_h3,
           const float* __restrict__ max_out, const float* __restrict__ max_rec,
           const int* __restrict__ idx_in,  const int* __restrict__ idx_h1,
           const int* __restrict__ idx_h2,  const int* __restrict__ idx_h3,
           const int* __restrict__ idx_out, const int* __restrict__ idx_rec,
           float* __restrict__ out) {
    __shared__ __align__(16) float As[2][16][68];
    __shared__ __align__(16) float Bs[2][16][68];

    const int bid = blockIdx.x;
    const int tid = threadIdx.x;
    const int tx  = tid & 15;
    const int ty  = tid >> 4;

    unsigned mygen = ((volatile unsigned*)&g_bargen)[0];

    // init recurrent state + norm partials to zero (every launch)
    for (int i = bid * NTH + tid; i < BB * XD; i += NB * NTH) g_rs[0][i] = 0.0f;
    if (bid == 0) {
        for (int i = tid; i < 16 * BB; i += NTH) ((float*)g_normpart)[i] = 0.0f;
    }
    gsync(mygen);

    // ================= Phase A: actin = act(x @ Wi^T + bi) ================
    // rows of x are (b*T + t); store permuted to (t*64 + b) so the time loop
    // reads contiguous [64, XD] blocks.
    for (int task = bid; task < 512 * 16; task += NB) {
        const int rt = task >> 4, nt = task & 15;
        float acc[4][4] = {};
        gemm_tile(x + (size_t)rt * 64 * IND, IND,
                  Wi + (size_t)nt * 64 * IND, IND, IND, acc, As, Bs);
        const int col0 = (nt << 6) + (tx << 2);
        const int4   id4 = __ldg((const int4*)&idx_in[col0]);
        const float4 mx4 = __ldg((const float4*)&max_in[col0]);
        const float4 b4  = __ldg((const float4*)&bi[col0]);
#pragma unroll
        for (int i = 0; i < 4; i++) {
            const int g = rt * 64 + (ty << 2) + i;
            const int b = g >> 9, t = g & 511;
            float4 v = make_float4(acc[i][0] + b4.x, acc[i][1] + b4.y,
                                   acc[i][2] + b4.z, acc[i][3] + b4.w);
            v = act4(v, id4, mx4);
            __stcg((float4*)&g_actin[(size_t)(t * BB + b) * XD + col0], v);
        }
    }
    gsync(mygen);

    // ================= Phase B: P = actin @ Wh1a^T + bh1 ==================
    for (int task = bid; task < 512 * 16; task += NB) {
        const int rt = task >> 4, nt = task & 15;
        float acc[4][4] = {};
        gemm_tile(g_actin + (size_t)rt * 64 * XD, XD,
                  Wh1 + (size_t)(nt << 6) * (2 * XD), 2 * XD, XD, acc, As, Bs);
        const int col0 = (nt << 6) + (tx << 2);
        const float4 b4 = __ldg((const float4*)&bh1[col0]);
#pragma unroll
        for (int i = 0; i < 4; i++) {
            const int row = rt * 64 + (ty << 2) + i;
            float4 v = make_float4(acc[i][0] + b4.x, acc[i][1] + b4.y,
                                   acc[i][2] + b4.z, acc[i][3] + b4.w);
            __stcg((float4*)&g_P[(size_t)row * XD + col0], v);
        }
    }
    gsync(mygen);

    // ================= time loop ==========================================
    for (int t = 0; t < TT; t++) {
        const int cur = t & 1, nxt = cur ^ 1;
        const float* Pt = g_P + (size_t)t * BB * XD;

        // ---- Phase 1: h1 = act( (rs@Wh1b^T)*rinv + P[t] ) ----
        {
            const int nt = bid >> 3, sp = bid & 7;
            const int n0 = nt << 6, k0 = sp << 7;
            float acc[4][4] = {};
            gemm_tile(g_rs[cur] + k0, XD,
                      Wh1 + XD + (size_t)n0 * (2 * XD) + k0, 2 * XD, 128, acc, As, Bs);
            if (ksplit_reduce(nt, sp, acc)) {
                const int col0 = n0 + (tx << 2);
                const int4   id4 = __ldg((const int4*)&idx_h1[col0]);
                const float4 mx4 = __ldg((const float4*)&max_h1[col0]);
#pragma unroll
                for (int i = 0; i < 4; i++) {
                    const int row = (ty << 2) + i;
                    float ss = 0.0f;
#pragma unroll
                    for (int pp = 0; pp < 16; pp++) ss += __ldcg(&g_normpart[pp][row]);
                    const float rinv = 1.0f / fmaxf(sqrtf(ss), 1e-12f);
                    const float4 p4 = __ldg((const float4*)&Pt[(size_t)row * XD + col0]);
                    float4 v = make_float4(acc[i][0] * rinv + p4.x, acc[i][1] * rinv + p4.y,
                                           acc[i][2] * rinv + p4.z, acc[i][3] * rinv + p4.w);
                    v = act4(v, id4, mx4);
                    __stcg((float4*)&g_h1[row * XD + col0], v);
                }
            }
        }
        gsync(mygen);

        // ---- Phase 2: h2 = act(h1 @ Wh2^T + bh2) ----
        {
            const int nt = bid >> 3, sp = bid & 7;
            const int n0 = nt << 6, k0 = sp << 7;
            float acc[4][4] = {};
            gemm_tile(g_h1 + k0, XD, Wh2 + (size_t)n0 * XD + k0, XD, 128, acc, As, Bs);
            if (ksplit_reduce(nt, sp, acc)) {
                const int col0 = n0 + (tx << 2);
                const int4   id4 = __ldg((const int4*)&idx_h2[col0]);
                const float4 mx4 = __ldg((const float4*)&max_h2[col0]);
                const float4 b4  = __ldg((const float4*)&bh2[col0]);
#pragma unroll
                for (int i = 0; i < 4; i++) {
                    const int row = (ty << 2) + i;
                    float4 v = make_float4(acc[i][0] + b4.x, acc[i][1] + b4.y,
                                           acc[i][2] + b4.z, acc[i][3] + b4.w);
                    v = act4(v, id4, mx4);
                    __stcg((float4*)&g_h2[row * XD + col0], v);
                }
            }
        }
        gsync(mygen);

        // ---- Phase 3: h3 = act(h2 @ Wh3^T + bh3) ----
        {
            const int nt = bid >> 3, sp = bid & 7;
            const int n0 = nt << 6, k0 = sp << 7;
            float acc[4][4] = {};
            gemm_tile(g_h2 + k0, XD, Wh3 + (size_t)n0 * XD + k0, XD, 128, acc, As, Bs);
            if (ksplit_reduce(nt, sp, acc)) {
                const int col0 = n0 + (tx << 2);
                const int4   id4 = __ldg((const int4*)&idx_h3[col0]);
                const float4 mx4 = __ldg((const float4*)&max_h3[col0]);
                const float4 b4  = __ldg((const float4*)&bh3[col0]);
#pragma unroll
                for (int i = 0; i < 4; i++) {
                    const int row = (ty << 2) + i;
                    float4 v = make_float4(acc[i][0] + b4.x, acc[i][1] + b4.y,
                                           acc[i][2] + b4.z, acc[i][3] + b4.w);
                    v = act4(v, id4, mx4);
                    __stcg((float4*)&g_h3[row * XD + col0], v);
                }
            }
        }
        gsync(mygen);

        // ---- Phase 4: rs_new = act(h3@Wr^T + br),  y[t] = act(h3@Wo^T + bo) ----
        for (int task = bid; task < 160; task += NB) {
            if (task < 128) {
                const int nt = task >> 3, sp = task & 7;
                const int n0 = nt << 6, k0 = sp << 7;
                float acc[4][4] = {};
                gemm_tile(g_h3 + k0, XD, Wr + (size_t)n0 * XD + k0, XD, 128, acc, As, Bs);
                if (ksplit_reduce(nt, sp, acc)) {
                    const int col0 = n0 + (tx << 2);
                    const int4   id4 = __ldg((const int4*)&idx_rec[col0]);
                    const float4 mx4 = __ldg((const float4*)&max_rec[col0]);
                    const float4 b4  = __ldg((const float4*)&br[col0]);
#pragma unroll
                    for (int i = 0; i < 4; i++) {
                        const int row = (ty << 2) + i;
                        float4 v = make_float4(acc[i][0] + b4.x, acc[i][1] + b4.y,
                                               acc[i][2] + b4.z, acc[i][3] + b4.w);
                        v = act4(v, id4, mx4);
                        __stcg((float4*)&g_rs[nxt][row * XD + col0], v);
                        float s = v.x * v.x + v.y * v.y + v.z * v.z + v.w * v.w;
                        s += __shfl_xor_sync(0xffffffffu, s, 1, 16);
                        s += __shfl_xor_sync(0xffffffffu, s, 2, 16);
                        s += __shfl_xor_sync(0xffffffffu, s, 4, 16);
                        s += __shfl_xor_sync(0xffffffffu, s, 8, 16);
                        if (tx == 0) __stcg(&g_normpart[nt][row], s);
                    }
                }
            } else {
                const int t2 = task - 128;
                const int nt = t2 >> 3, sp = t2 & 7;
                const int n0 = nt << 6, k0 = sp << 7;
                float acc[4][4] = {};
                gemm_tile(g_h3 + k0, XD, Wo + (size_t)n0 * XD + k0, XD, 128, acc, As, Bs);
                if (ksplit_reduce(16 + nt, sp, acc)) {
                    const int col0 = n0 + (tx << 2);
                    const int4   id4 = __ldg((const int4*)&idx_out[col0]);
                    const float4 mx4 = __ldg((const float4*)&max_out[col0]);
                    const float4 b4  = __ldg((const float4*)&bo[col0]);
#pragma unroll
                    for (int i = 0; i < 4; i++) {
                        const int row = (ty << 2) + i;  // batch index
                        float4 v = make_float4(acc[i][0] + b4.x, acc[i][1] + b4.y,
                                               acc[i][2] + b4.z, acc[i][3] + b4.w);
                        v = act4(v, id4, mx4);
                        __stcg((float4*)&out[((size_t)row * TT + t) * OUTD + col0], v);
                    }
                }
            }
        }
        gsync(mygen);
    }
}

// ------------------------- launch ------------------------------------------
extern "C" void kernel_launch(void* const* d_in, const int* in_sizes, int n_in,
                              void* d_out, int out_size) {
    const float* x       = (const float*)d_in[0];
    const float* Wi      = (const float*)d_in[1];
    const float* bi      = (const float*)d_in[2];
    const float* Wh1     = (const float*)d_in[3];
    const float* bh1     = (const float*)d_in[4];
    const float* Wh2     = (const float*)d_in[5];
    const float* bh2     = (const float*)d_in[6];
    const float* Wh3     = (const float*)d_in[7];
    const float* bh3     = (const float*)d_in[8];
    const float* Wo      = (const float*)d_in[9];
    const float* bo      = (const float*)d_in[10];
    const float* Wr      = (const float*)d_in[11];
    const float* br      = (const float*)d_in[12];
    const float* max_in  = (const float*)d_in[13];
    const float* max_h1  = (const float*)d_in[14];
    const float* max_h2  = (const float*)d_in[15];
    const float* max_h3  = (const float*)d_in[16];
    const float* max_out = (const float*)d_in[17];
    const float* max_rec = (const float*)d_in[18];
    const int*   idx_in  = (const int*)d_in[19];
    const int*   idx_h1  = (const int*)d_in[20];
    const int*   idx_h2  = (const int*)d_in[21];
    const int*   idx_h3  = (const int*)d_in[22];
    const int*   idx_out = (const int*)d_in[23];
    const int*   idx_rec = (const int*)d_in[24];

    bnn_kernel<<<NB, NTH>>>(x, Wi, bi, Wh1, bh1, Wh2, bh2, Wh3, bh3, Wo, bo, Wr, br,
                            max_in, max_h1, max_h2, max_h3, max_out, max_rec,
                            idx_in, idx_h1, idx_h2, idx_h3, idx_out, idx_rec,
                            (float*)d_out);
}

// round 5
// speedup vs baseline: 1.3358x; 1.3358x over previous
#include <cuda_runtime.h>
#include <math.h>

#define NB    128
#define NTH   512
#define BB    64
#define TT    512
#define IND   512
#define XD    1024
#define OUTD  256

// ------------------------- device scratch ---------------------------------
__device__ float g_actin[(size_t)BB * TT * XD];   // [t*64+b][XD]
__device__ float g_P[(size_t)BB * TT * XD];       // [t*64+b][XD]
__device__ float g_h3all[(size_t)TT * BB * XD];   // [t][b][XD]
__device__ float g_h1[BB * XD];
__device__ float g_h2[BB * XD];
__device__ float g_rs[BB * XD];
__device__ float g_normpart[BB][16];              // [row][tile] partial sumsq of rs
__device__ float g_part[64 * 8 * 4096];           // (phase*16+tile, sp) partial slabs
__device__ unsigned g_cnt[64];                    // per (phase,tile) arrival counters
__device__ unsigned g_flag[4][16 * 32];           // epoch flags, padded 128B apart
__device__ unsigned g_barcnt;
__device__ unsigned g_bargen;

// ------------------------- activation (matches reference) -----------------
__device__ __forceinline__ float rand_act(float v, int idx, float mx) {
    float r;
    switch (idx) {
    case 0:  r = fmaxf(v, 0.0f); break;
    case 1:  r = 1.0f / (1.0f + expf(-v)); break;
    case 2:  r = tanhf(v); break;
    case 3:  r = (v >= 0.0f) ? v : 0.1f * v; break;
    default: {
        const float a = 1.6732632423543772f, s = 1.0507009873554805f;
        r = (v > 0.0f) ? s * v : s * a * expm1f(v);
    } break;
    }
    return fminf(r, mx);
}

__device__ __forceinline__ float4 act4(float4 v, int4 id, float4 mx) {
    return make_float4(rand_act(v.x, id.x, mx.x), rand_act(v.y, id.y, mx.y),
                       rand_act(v.z, id.z, mx.z), rand_act(v.w, id.w, mx.w));
}

// ------------------------- grid-wide barrier (pre/post loop only) ----------
__device__ __forceinline__ void gsync(unsigned& mygen) {
    __threadfence();
    __syncthreads();
    if (threadIdx.x == 0) {
        unsigned old = atomicAdd(&g_barcnt, 1u);
        if (old == NB - 1u) {
            g_barcnt = 0u;
            __threadfence();
            atomicAdd(&g_bargen, 1u);
        } else {
            while (((volatile unsigned*)&g_bargen)[0] == mygen) { __nanosleep(64); }
        }
    }
    __syncthreads();
    mygen += 1u;
}

// ------------------------- dataflow wait ----------------------------------
__device__ __forceinline__ void wait2(volatile unsigned* f, int a, int b, unsigned tgt) {
    if (threadIdx.x == 0) {
        while (f[a * 32] < tgt) { __nanosleep(32); }
        while (f[b * 32] < tgt) { __nanosleep(32); }
    }
    __syncthreads();
}

__device__ __forceinline__ void publish(volatile unsigned* f, unsigned v) {
    __threadfence();
    __syncthreads();
    if (threadIdx.x == 0) *f = v;
}

// ------------------------- 64x64 tile GEMM, 512 threads --------------------
// C[64,64] = A(64 x K) * B(64 x K)^T ; per-thread acc[2][4].
// A via __ldcg (mutable), B via __ldg (constant weights).
__device__ __forceinline__ void gemm512(const float* __restrict__ Ap, int lda,
                                        const float* __restrict__ Bp, int ldb,
                                        int K, float acc[2][4],
                                        float (&As)[2][32][68], float (&Bs)[2][32][68],
                                        int tx, int ty) {
    const int tid  = threadIdx.x;
    const int lrow = tid >> 3;          // 0..63
    const int lk   = (tid & 7) << 2;    // 0,4,...,28
    const float* aptr = Ap + (size_t)lrow * lda + lk;
    const float* bptr = Bp + (size_t)lrow * ldb + lk;

    float4 av = __ldcg((const float4*)aptr);
    float4 bv = __ldg((const float4*)bptr);
    int p = 0;
    for (int kc = 0; kc < K; kc += 32) {
        As[p][lk + 0][lrow] = av.x; As[p][lk + 1][lrow] = av.y;
        As[p][lk + 2][lrow] = av.z; As[p][lk + 3][lrow] = av.w;
        Bs[p][lk + 0][lrow] = bv.x; Bs[p][lk + 1][lrow] = bv.y;
        Bs[p][lk + 2][lrow] = bv.z; Bs[p][lk + 3][lrow] = bv.w;
        __syncthreads();
        if (kc + 32 < K) {
            av = __ldcg((const float4*)(aptr + kc + 32));
            bv = __ldg((const float4*)(bptr + kc + 32));
        }
#pragma unroll
        for (int kk = 0; kk < 32; kk++) {
            float2 a = *(const float2*)&As[p][kk][ty << 1];
            float4 b = *(const float4*)&Bs[p][kk][tx << 2];
            acc[0][0] += a.x * b.x; acc[0][1] += a.x * b.y;
            acc[0][2] += a.x * b.z; acc[0][3] += a.x * b.w;
            acc[1][0] += a.y * b.x; acc[1][1] += a.y * b.y;
            acc[1][2] += a.y * b.z; acc[1][3] += a.y * b.w;
        }
        p ^= 1;
    }
    __syncthreads();   // protect shared reuse by next call
}

// ------------------------- k-split finish ----------------------------------
__device__ __forceinline__ bool ksplit(int slot, int sp, float acc[2][4], int tx, int ty) {
    float* slab = &g_part[((size_t)slot * 8 + sp) * 4096];
#pragma unroll
    for (int i = 0; i < 2; i++) {
        float4 v = make_float4(acc[i][0], acc[i][1], acc[i][2], acc[i][3]);
        __stcg((float4*)&slab[((ty << 1) + i) * 64 + (tx << 2)], v);
    }
    __threadfence();
    __syncthreads();
    __shared__ int s_last;
    if (threadIdx.x == 0) {
        unsigned old = atomicAdd(&g_cnt[slot], 1u);
        s_last = (old == 7u);
        if (old == 7u) g_cnt[slot] = 0u;
    }
    __syncthreads();
    if (!s_last) return false;
    __threadfence();
#pragma unroll
    for (int s = 0; s < 8; s++) {
        if (s == sp) continue;
        const float* os = &g_part[((size_t)slot * 8 + s) * 4096];
#pragma unroll
        for (int i = 0; i < 2; i++) {
            float4 pv = __ldcg((const float4*)&os[((ty << 1) + i) * 64 + (tx << 2)]);
            acc[i][0] += pv.x; acc[i][1] += pv.y; acc[i][2] += pv.z; acc[i][3] += pv.w;
        }
    }
    return true;
}

// ------------------------- main persistent kernel --------------------------
__global__ void __launch_bounds__(NTH, 1)
bnn_kernel(const float* __restrict__ x,
           const float* __restrict__ Wi,  const float* __restrict__ bi,
           const float* __restrict__ Wh1, const float* __restrict__ bh1,
           const float* __restrict__ Wh2, const float* __restrict__ bh2,
           const float* __restrict__ Wh3, const float* __restrict__ bh3,
           const float* __restrict__ Wo,  const float* __restrict__ bo,
           const float* __restrict__ Wr,  const float* __restrict__ br,
           const float* __restrict__ max_in,  const float* __restrict__ max_h1,
           const float* __restrict__ max_h2,  const float* __restrict__ max_h3,
           const float* __restrict__ max_out, const float* __restrict__ max_rec,
           const int* __restrict__ idx_in,  const int* __restrict__ idx_h1,
           const int* __restrict__ idx_h2,  const int* __restrict__ idx_h3,
           const int* __restrict__ idx_out, const int* __restrict__ idx_rec,
           float* __restrict__ out) {
    __shared__ __align__(16) float As[2][32][68];
    __shared__ __align__(16) float Bs[2][32][68];

    const int bid = blockIdx.x;
    const int tid = threadIdx.x;
    const int tx  = tid & 15;          // output col group (4 cols)
    const int ty  = tid >> 4;          // output row group (2 rows), 0..31

    unsigned mygen = ((volatile unsigned*)&g_bargen)[0];

    // ---- init state (every launch) ----
    {
        int i = bid * NTH + tid;           // exactly BB*XD = 65536 threads
        g_rs[i] = 0.0f;
        if (bid == 0) {
            for (int j = tid; j < BB * 16; j += NTH) ((float*)g_normpart)[j] = 0.0f;
            for (int j = tid; j < 4 * 16 * 32; j += NTH) ((unsigned*)g_flag)[j] = 0u;
            if (tid < 64) g_cnt[tid] = 0u;
        }
    }
    gsync(mygen);

    // ================= Phase A: actin = act(x @ Wi^T + bi), permuted =======
    for (int task = bid; task < 512 * 16; task += NB) {
        const int rt = task >> 4, nt = task & 15;
        float acc[2][4] = {};
        gemm512(x + (size_t)rt * 64 * IND, IND,
                Wi + (size_t)(nt << 6) * IND, IND, IND, acc, As, Bs, tx, ty);
        const int col0 = (nt << 6) + (tx << 2);
        const int4   id4 = __ldg((const int4*)&idx_in[col0]);
        const float4 mx4 = __ldg((const float4*)&max_in[col0]);
        const float4 b4  = __ldg((const float4*)&bi[col0]);
#pragma unroll
        for (int i = 0; i < 2; i++) {
            const int g = rt * 64 + (ty << 1) + i;
            const int b = g >> 9, t = g & 511;
            float4 v = make_float4(acc[i][0] + b4.x, acc[i][1] + b4.y,
                                   acc[i][2] + b4.z, acc[i][3] + b4.w);
            v = act4(v, id4, mx4);
            __stcg((float4*)&g_actin[(size_t)(t * BB + b) * XD + col0], v);
        }
    }
    gsync(mygen);

    // ================= Phase B: P = actin @ Wh1a^T + bh1 ===================
    for (int task = bid; task < 512 * 16; task += NB) {
        const int rt = task >> 4, nt = task & 15;
        float acc[2][4] = {};
        gemm512(g_actin + (size_t)rt * 64 * XD, XD,
                Wh1 + (size_t)(nt << 6) * (2 * XD), 2 * XD, XD, acc, As, Bs, tx, ty);
        const int col0 = (nt << 6) + (tx << 2);
        const float4 b4 = __ldg((const float4*)&bh1[col0]);
#pragma unroll
        for (int i = 0; i < 2; i++) {
            const int row = rt * 64 + (ty << 1) + i;
            float4 v = make_float4(acc[i][0] + b4.x, acc[i][1] + b4.y,
                                   acc[i][2] + b4.z, acc[i][3] + b4.w);
            __stcg((float4*)&g_P[(size_t)row * XD + col0], v);
        }
    }
    gsync(mygen);

    // ================= time loop (dataflow, no grid barriers) ==============
    const int nt = bid >> 3;           // output tile 0..15
    const int sp = bid & 7;            // k-split 0..7
    const int n0 = nt << 6;
    const int k0 = sp << 7;
    const int col0 = n0 + (tx << 2);

    for (int s = 0; s < TT; s++) {
        // ---- Phase 1: h1 = act( (rs@Wh1b^T)*rinv + P[s] ) ----
        wait2(g_flag[3], 2 * sp, 2 * sp + 1, (unsigned)s);
        {
            float acc[2][4] = {};
            gemm512(g_rs + k0, XD,
                    Wh1 + XD + (size_t)n0 * (2 * XD) + k0, 2 * XD, 128, acc, As, Bs, tx, ty);
            if (ksplit(0 * 16 + nt, sp, acc, tx, ty)) {
                const int4   id4 = __ldg((const int4*)&idx_h1[col0]);
                const float4 mx4 = __ldg((const float4*)&max_h1[col0]);
                const float* Pt = g_P + (size_t)s * BB * XD;
#pragma unroll
                for (int i = 0; i < 2; i++) {
                    const int row = (ty << 1) + i;
                    float4 n0v = __ldcg((const float4*)&g_normpart[row][0]);
                    float4 n1v = __ldcg((const float4*)&g_normpart[row][4]);
                    float4 n2v = __ldcg((const float4*)&g_normpart[row][8]);
                    float4 n3v = __ldcg((const float4*)&g_normpart[row][12]);
                    float ss = ((n0v.x + n0v.y) + (n0v.z + n0v.w))
                             + ((n1v.x + n1v.y) + (n1v.z + n1v.w))
                             + ((n2v.x + n2v.y) + (n2v.z + n2v.w))
                             + ((n3v.x + n3v.y) + (n3v.z + n3v.w));
                    const float rinv = 1.0f / fmaxf(sqrtf(ss), 1e-12f);
                    const float4 p4 = __ldg((const float4*)&Pt[(size_t)row * XD + col0]);
                    float4 v = make_float4(acc[i][0] * rinv + p4.x, acc[i][1] * rinv + p4.y,
                                           acc[i][2] * rinv + p4.z, acc[i][3] * rinv + p4.w);
                    v = act4(v, id4, mx4);
                    __stcg((float4*)&g_h1[row * XD + col0], v);
                }
                publish(&g_flag[0][nt * 32], (unsigned)(s + 1));
            }
        }

        // ---- Phase 2: h2 = act(h1 @ Wh2^T + bh2) ----
        wait2(g_flag[0], 2 * sp, 2 * sp + 1, (unsigned)(s + 1));
        {
            float acc[2][4] = {};
            gemm512(g_h1 + k0, XD, Wh2 + (size_t)n0 * XD + k0, XD, 128, acc, As, Bs, tx, ty);
            if (ksplit(1 * 16 + nt, sp, acc, tx, ty)) {
                const int4   id4 = __ldg((const int4*)&idx_h2[col0]);
                const float4 mx4 = __ldg((const float4*)&max_h2[col0]);
                const float4 b4  = __ldg((const float4*)&bh2[col0]);
#pragma unroll
                for (int i = 0; i < 2; i++) {
                    const int row = (ty << 1) + i;
                    float4 v = make_float4(acc[i][0] + b4.x, acc[i][1] + b4.y,
                                           acc[i][2] + b4.z, acc[i][3] + b4.w);
                    v = act4(v, id4, mx4);
                    __stcg((float4*)&g_h2[row * XD + col0], v);
                }
                publish(&g_flag[1][nt * 32], (unsigned)(s + 1));
            }
        }

        // ---- Phase 3: h3all[s] = act(h2 @ Wh3^T + bh3) ----
        wait2(g_flag[1], 2 * sp, 2 * sp + 1, (unsigned)(s + 1));
        {
            float acc[2][4] = {};
            gemm512(g_h2 + k0, XD, Wh3 + (size_t)n0 * XD + k0, XD, 128, acc, As, Bs, tx, ty);
            if (ksplit(2 * 16 + nt, sp, acc, tx, ty)) {
                const int4   id4 = __ldg((const int4*)&idx_h3[col0]);
                const float4 mx4 = __ldg((const float4*)&max_h3[col0]);
                const float4 b4  = __ldg((const float4*)&bh3[col0]);
                float* h3t = g_h3all + (size_t)s * BB * XD;
#pragma unroll
                for (int i = 0; i < 2; i++) {
                    const int row = (ty << 1) + i;
                    float4 v = make_float4(acc[i][0] + b4.x, acc[i][1] + b4.y,
                                           acc[i][2] + b4.z, acc[i][3] + b4.w);
                    v = act4(v, id4, mx4);
                    __stcg((float4*)&h3t[row * XD + col0], v);
                }
                publish(&g_flag[2][nt * 32], (unsigned)(s + 1));
            }
        }

        // ---- Phase 4: rs = act(h3 @ Wr^T + br) + normpart ----
        wait2(g_flag[2], 2 * sp, 2 * sp + 1, (unsigned)(s + 1));
        {
            float acc[2][4] = {};
            gemm512(g_h3all + (size_t)s * BB * XD + k0, XD,
                    Wr + (size_t)n0 * XD + k0, XD, 128, acc, As, Bs, tx, ty);
            if (ksplit(3 * 16 + nt, sp, acc, tx, ty)) {
                const int4   id4 = __ldg((const int4*)&idx_rec[col0]);
                const float4 mx4 = __ldg((const float4*)&max_rec[col0]);
                const float4 b4  = __ldg((const float4*)&br[col0]);
#pragma unroll
                for (int i = 0; i < 2; i++) {
                    const int row = (ty << 1) + i;
                    float4 v = make_float4(acc[i][0] + b4.x, acc[i][1] + b4.y,
                                           acc[i][2] + b4.z, acc[i][3] + b4.w);
                    v = act4(v, id4, mx4);
                    __stcg((float4*)&g_rs[row * XD + col0], v);
                    float sq = v.x * v.x + v.y * v.y + v.z * v.z + v.w * v.w;
                    sq += __shfl_xor_sync(0xffffffffu, sq, 1, 16);
                    sq += __shfl_xor_sync(0xffffffffu, sq, 2, 16);
                    sq += __shfl_xor_sync(0xffffffffu, sq, 4, 16);
                    sq += __shfl_xor_sync(0xffffffffu, sq, 8, 16);
                    if (tx == 0) __stcg(&g_normpart[row][nt], sq);
                }
                publish(&g_flag[3][nt * 32], (unsigned)(s + 1));
            }
        }
    }
    gsync(mygen);

    // ================= Output GEMM: y = act(H3 @ Wo^T + bo) ================
    for (int task = bid; task < 512 * 4; task += NB) {
        const int t = task >> 2, ot = task & 3;
        float acc[2][4] = {};
        gemm512(g_h3all + (size_t)t * BB * XD, XD,
                Wo + (size_t)(ot << 6) * XD, XD, XD, acc, As, Bs, tx, ty);
        const int oc0 = (ot << 6) + (tx << 2);
        const int4   id4 = __ldg((const int4*)&idx_out[oc0]);
        const float4 mx4 = __ldg((const float4*)&max_out[oc0]);
        const float4 b4  = __ldg((const float4*)&bo[oc0]);
#pragma unroll
        for (int i = 0; i < 2; i++) {
            const int b = (ty << 1) + i;   // batch row
            float4 v = make_float4(acc[i][0] + b4.x, acc[i][1] + b4.y,
                                   acc[i][2] + b4.z, acc[i][3] + b4.w);
            v = act4(v, id4, mx4);
            __stcg((float4*)&out[((size_t)b * TT + t) * OUTD + oc0], v);
        }
    }
}

// ------------------------- launch ------------------------------------------
extern "C" void kernel_launch(void* const* d_in, const int* in_sizes, int n_in,
                              void* d_out, int out_size) {
    const float* x       = (const float*)d_in[0];
    const float* Wi      = (const float*)d_in[1];
    const float* bi      = (const float*)d_in[2];
    const float* Wh1     = (const float*)d_in[3];
    const float* bh1     = (const float*)d_in[4];
    const float* Wh2     = (const float*)d_in[5];
    const float* bh2     = (const float*)d_in[6];
    const float* Wh3     = (const float*)d_in[7];
    const float* bh3     = (const float*)d_in[8];
    const float* Wo      = (const float*)d_in[9];
    const float* bo      = (const float*)d_in[10];
    const float* Wr      = (const float*)d_in[11];
    const float* br      = (const float*)d_in[12];
    const float* max_in  = (const float*)d_in[13];
    const float* max_h1  = (const float*)d_in[14];
    const float* max_h2  = (const float*)d_in[15];
    const float* max_h3  = (const float*)d_in[16];
    const float* max_out = (const float*)d_in[17];
    const float* max_rec = (const float*)d_in[18];
    const int*   idx_in  = (const int*)d_in[19];
    const int*   idx_h1  = (const int*)d_in[20];
    const int*   idx_h2  = (const int*)d_in[21];
    const int*   idx_h3  = (const int*)d_in[22];
    const int*   idx_out = (const int*)d_in[23];
    const int*   idx_rec = (const int*)d_in[24];

    bnn_kernel<<<NB, NTH>>>(x, Wi, bi, Wh1, bh1, Wh2, bh2, Wh3, bh3, Wo, bo, Wr, br,
                            max_in, max_h1, max_h2, max_h3, max_out, max_rec,
                            idx_in, idx_h1, idx_h2, idx_h3, idx_out, idx_rec,
                            (float*)d_out);
}